// round 8
// baseline (speedup 1.0000x reference)
#include <cuda_runtime.h>
#include <cuda_fp16.h>

#define STR 128            // shared row stride (floats) — all accesses lane-consecutive/broadcast
#define THREADS 512
#define GT 256             // threads per group
#define TROWS 64           // tile rows per group

// ---------------- f32x2 helpers (sm_103a packed fp32 FFMA2) ----------------
__device__ __forceinline__ unsigned long long dup_f32x2(float a) {
    unsigned long long r;
    unsigned int ai = __float_as_uint(a);
    asm("mov.b64 %0, {%1, %1};" : "=l"(r) : "r"(ai));
    return r;
}
__device__ __forceinline__ void fma2(unsigned long long &acc, unsigned long long a, unsigned long long b) {
    asm("fma.rn.f32x2 %0, %1, %2, %0;" : "+l"(acc) : "l"(a), "l"(b));
}
__device__ __forceinline__ float2 unpack2(unsigned long long v) {
    unsigned int lo, hi;
    asm("mov.b64 {%0, %1}, %2;" : "=r"(lo), "=r"(hi) : "l"(v));
    return make_float2(__uint_as_float(lo), __uint_as_float(hi));
}
__device__ __forceinline__ void gbar(int id) {
    asm volatile("bar.sync %0, %1;" :: "r"(id), "r"(GT) : "memory");
}

// Lloyd-Max bucketize (matches jnp.searchsorted side='left' over interior boundaries)
__device__ __forceinline__ float quantize1(float v, const float* __restrict__ sB,
                                           const float* __restrict__ sC) {
    int idx = (v > sB[8]) ? 8 : 0;
    idx += (v > sB[idx + 4]) ? 4 : 0;
    idx += (v > sB[idx + 2]) ? 2 : 0;
    idx += (v > sB[idx + 1]) ? 1 : 0;
    return sC[idx];
}

__global__ __launch_bounds__(THREADS, 1)
void tq_kernel(const float* __restrict__ x, const float* __restrict__ Pi,
               const float* __restrict__ cen, const float* __restrict__ bnd,
               float* __restrict__ out, int n_tiles)
{
    extern __shared__ float smem[];
    float* sPi  = smem;                    // [128][STR] Pi[j][k]
    float* sPiT = sPi  + 128 * STR;        // [128][STR] PiT[k][j]
    float* sXg  = sPiT + 128 * STR;        // [2][TROWS][STR] per-group x/values tile
    float* sRng = sXg  + 2 * TROWS * STR;  // [2][TROWS]
    float* sNqg = sRng + 2 * TROWS;        // [2][TROWS]
    float* sB   = sNqg + 2 * TROWS;        // [16]
    float* sC   = sB   + 16;               // [16]

    const int tid   = threadIdx.x;
    const int group = tid >> 8;            // 0 or 1
    const int gt    = tid & 255;           // thread-in-group
    const int w     = gt >> 5;             // warp-in-group 0..7 -> rows w*8..w*8+7
    const int lane  = gt & 31;             // lane -> cols lane*4..+3
    const int r0    = w * 8;
    const int c0    = lane * 4;

    float* sX  = sXg  + group * TROWS * STR;
    float* sRn = sRng + group * TROWS;
    float* sNq = sNqg + group * TROWS;
    const int barid = group + 1;

    // ---- stage Pi and PiT once per block (all 512 threads) ----
    #pragma unroll
    for (int it = 0; it < 8; ++it) {
        int idx = it * THREADS + tid;      // 4096 float4 total
        int r = idx >> 5, c4 = idx & 31;
        float4 v = reinterpret_cast<const float4*>(Pi)[idx];
        *reinterpret_cast<float4*>(&sPi[r * STR + c4 * 4]) = v;
        sPiT[(c4 * 4 + 0) * STR + r] = v.x;
        sPiT[(c4 * 4 + 1) * STR + r] = v.y;
        sPiT[(c4 * 4 + 2) * STR + r] = v.z;
        sPiT[(c4 * 4 + 3) * STR + r] = v.w;
    }
    if (tid < 16) sC[tid] = cen[tid];
    if (tid < 16) sB[tid] = bnd[tid];
    __syncthreads();

    const int stride = gridDim.x * 2;
    for (int tile = blockIdx.x * 2 + group; tile < n_tiles; tile += stride) {
        const float* gx   = x   + (size_t)tile * TROWS * 128;
        float*       gout = out + (size_t)tile * TROWS * 128;

        gbar(barid);   // prev iteration's GEMM2 reads of sX are done

        // ---- stage x tile + fused per-row norms (warp-per-row, shfl reduce) ----
        #pragma unroll
        for (int it = 0; it < 8; ++it) {
            int idx = it * GT + gt;
            int r = idx >> 5;              // = it*8 + w (warp-uniform)
            float4 v = reinterpret_cast<const float4*>(gx)[idx];
            *reinterpret_cast<float4*>(&sX[r * STR + lane * 4]) = v;
            float s = v.x * v.x + v.y * v.y + v.z * v.z + v.w * v.w;
            s += __shfl_xor_sync(0xffffffffu, s, 16);
            s += __shfl_xor_sync(0xffffffffu, s, 8);
            s += __shfl_xor_sync(0xffffffffu, s, 4);
            s += __shfl_xor_sync(0xffffffffu, s, 2);
            s += __shfl_xor_sync(0xffffffffu, s, 1);
            if (lane == 0) {
                float nrm = sqrtf(s);
                sRn[r] = 1.0f / (nrm + 1e-8f);
                sNq[r] = __half2float(__float2half_rn(nrm));
            }
        }
        gbar(barid);

        // ---- GEMM 1: rot[r][j] = sum_k x[r][k] * Pi[j][k]
        //      thread: rows r0..r0+7, cols c0..c0+3 (warp spans 128 cols) ----
        unsigned long long acc[8][2];
        #pragma unroll
        for (int i = 0; i < 8; ++i) { acc[i][0] = 0ull; acc[i][1] = 0ull; }

        #pragma unroll 8
        for (int kb = 0; kb < 32; ++kb) {
            float4 av[8];
            #pragma unroll
            for (int i = 0; i < 8; ++i)
                av[i] = *reinterpret_cast<const float4*>(&sX[(r0 + i) * STR + kb * 4]);
            #pragma unroll
            for (int t = 0; t < 4; ++t) {
                ulonglong2 b = *reinterpret_cast<const ulonglong2*>(&sPiT[(kb * 4 + t) * STR + c0]);
                #pragma unroll
                for (int i = 0; i < 8; ++i) {
                    float a = (t == 0) ? av[i].x : (t == 1) ? av[i].y : (t == 2) ? av[i].z : av[i].w;
                    unsigned long long ad = dup_f32x2(a);
                    fma2(acc[i][0], ad, b.x);
                    fma2(acc[i][1], ad, b.y);
                }
            }
        }

        gbar(barid);   // all reads of x tile done before overwrite

        // ---- quantize (fused) -> values tile ----
        #pragma unroll
        for (int i = 0; i < 8; ++i) {
            int r = r0 + i;
            float rnv = sRn[r];
            float2 p0 = unpack2(acc[i][0]);
            float2 p1 = unpack2(acc[i][1]);
            float4 q;
            q.x = quantize1(p0.x * rnv, sB, sC);
            q.y = quantize1(p0.y * rnv, sB, sC);
            q.z = quantize1(p1.x * rnv, sB, sC);
            q.w = quantize1(p1.y * rnv, sB, sC);
            *reinterpret_cast<float4*>(&sX[r * STR + c0]) = q;
        }
        gbar(barid);

        // ---- GEMM 2: recon[r][k] = sum_j values[r][j] * Pi[j][k] ----
        #pragma unroll
        for (int i = 0; i < 8; ++i) { acc[i][0] = 0ull; acc[i][1] = 0ull; }

        #pragma unroll 8
        for (int jb = 0; jb < 32; ++jb) {
            float4 av[8];
            #pragma unroll
            for (int i = 0; i < 8; ++i)
                av[i] = *reinterpret_cast<const float4*>(&sX[(r0 + i) * STR + jb * 4]);
            #pragma unroll
            for (int t = 0; t < 4; ++t) {
                ulonglong2 b = *reinterpret_cast<const ulonglong2*>(&sPi[(jb * 4 + t) * STR + c0]);
                #pragma unroll
                for (int i = 0; i < 8; ++i) {
                    float a = (t == 0) ? av[i].x : (t == 1) ? av[i].y : (t == 2) ? av[i].z : av[i].w;
                    unsigned long long ad = dup_f32x2(a);
                    fma2(acc[i][0], ad, b.x);
                    fma2(acc[i][1], ad, b.y);
                }
            }
        }

        // ---- scale by fp16-roundtripped norm, store coalesced ----
        #pragma unroll
        for (int i = 0; i < 8; ++i) {
            int r = r0 + i;
            float nq = sNq[r];
            float2 p0 = unpack2(acc[i][0]);
            float2 p1 = unpack2(acc[i][1]);
            float4 o = make_float4(p0.x * nq, p0.y * nq, p1.x * nq, p1.y * nq);
            *reinterpret_cast<float4*>(&gout[r * 128 + c0]) = o;
        }
    }
}

extern "C" void kernel_launch(void* const* d_in, const int* in_sizes, int n_in,
                              void* d_out, int out_size) {
    const float* x   = (const float*)d_in[0];
    const float* Pi  = (const float*)d_in[1];
    const float* cen = (const float*)d_in[2];
    const float* bnd = (const float*)d_in[3];
    float* out = (float*)d_out;

    int N = in_sizes[0] / 128;
    int n_tiles = N / TROWS;

    int nsm = 148;
    cudaDeviceGetAttribute(&nsm, cudaDevAttrMultiProcessorCount, 0);
    if (nsm <= 0) nsm = 148;

    size_t smem_bytes = (size_t)(2 * 128 * STR + 2 * TROWS * STR + 4 * TROWS + 32) * sizeof(float);
    cudaFuncSetAttribute(tq_kernel, cudaFuncAttributeMaxDynamicSharedMemorySize, (int)smem_bytes);

    tq_kernel<<<nsm, THREADS, smem_bytes>>>(x, Pi, cen, bnd, out, n_tiles);
}